// round 9
// baseline (speedup 1.0000x reference)
#include <cuda_runtime.h>

#define BB   8
#define LSEQ 4096
#define CDIM 256
#define DI   512
#define E2   1024
#define NTOK (BB*LSEQ)

__device__ float g_xn  [NTOK*CDIM];
__device__ float g_xz  [(size_t)NTOK*E2];
__device__ float g_xcf [NTOK*DI];
__device__ float g_xcr [NTOK*DI];
__device__ float g_dblf[NTOK*48];
__device__ float g_dblr[NTOK*48];
__device__ float g_yf  [NTOK*DI];
__device__ float g_yr  [NTOK*DI];
__device__ float g_mo  [NTOK*CDIM];
__device__ float g_xmn [NTOK*CDIM];

// ---- LayerNorm over c of x[b,c,l] (+optional mo[b,l,c] + skip) -> out[b,l,c] ----
template<bool ADD_MO>
__global__ void ln_kernel(const float* __restrict__ x,
                          const float* __restrict__ g,
                          const float* __restrict__ be,
                          const float* __restrict__ skip,
                          float* __restrict__ out)
{
    __shared__ float sm[256][33];
    __shared__ float smean[32], srstd[32];
    int l0 = blockIdx.x * 32, b = blockIdx.y, tid = threadIdx.x;
    const float* xb = x + (size_t)b*CDIM*LSEQ;
    #pragma unroll
    for (int i = 0; i < 32; i++) {
        int idx = tid + i*256, c = idx >> 5, li = idx & 31;
        sm[c][li] = xb[(size_t)c*LSEQ + l0 + li];
    }
    __syncthreads();
    float sk = ADD_MO ? skip[0] : 0.f;
    const float* mo = g_mo + ((size_t)b*LSEQ + l0)*CDIM;
    int w = tid >> 5, lane = tid & 31;
    for (int li = w; li < 32; li += 8) {
        float s = 0.f, s2 = 0.f;
        #pragma unroll
        for (int j = 0; j < 8; j++) {
            int c = lane + (j << 5);
            float v = sm[c][li];
            if (ADD_MO) { v = fmaf(sk, v, mo[(size_t)li*CDIM + c]); sm[c][li] = v; }
            s += v; s2 += v*v;
        }
        #pragma unroll
        for (int off = 16; off; off >>= 1) {
            s  += __shfl_xor_sync(0xffffffffu, s,  off);
            s2 += __shfl_xor_sync(0xffffffffu, s2, off);
        }
        if (lane == 0) {
            float m = s * (1.f/256.f);
            smean[li] = m;
            srstd[li] = rsqrtf(s2*(1.f/256.f) - m*m + 1e-5f);
        }
    }
    __syncthreads();
    float* op = out + ((size_t)b*LSEQ + l0)*CDIM;
    #pragma unroll
    for (int i = 0; i < 32; i++) {
        int idx = tid + i*256, li = idx >> 8, c = idx & 255;
        op[(size_t)li*CDIM + c] = (sm[c][li] - smean[li])*srstd[li]*g[c] + be[c];
    }
}

// ---- causal depthwise conv + SiLU, both directions ----
__global__ void conv_kernel(const float* __restrict__ cwf, const float* __restrict__ cbf,
                            const float* __restrict__ cwr, const float* __restrict__ cbr)
{
    int idx = blockIdx.x*256 + threadIdx.x;
    int d = idx & (DI-1), l = (idx >> 9) & (LSEQ-1), b = (idx >> 21) & 7, dir = idx >> 24;
    const float* w = (dir ? cwr : cwf) + d*4;
    float acc = (dir ? cbr : cbf)[d];
    const float* xzb = g_xz + (size_t)b*LSEQ*E2 + d;
    #pragma unroll
    for (int j = 0; j < 4; j++) {
        int ir = l - 3 + j;
        if (ir >= 0) {
            int ls = dir ? (LSEQ-1-ir) : ir;
            acc = fmaf(w[j], xzb[(size_t)ls*E2], acc);
        }
    }
    float s = __fdividef(acc, 1.f + __expf(-acc));
    (dir ? g_xcr : g_xcf)[((size_t)b*LSEQ + l)*DI + d] = s;
}

// ---- selective scan: one thread per (dir,b,d) ----
__global__ void __launch_bounds__(32)
scan_kernel(const float* __restrict__ dtw_f, const float* __restrict__ dtb_f,
            const float* __restrict__ alog_f, const float* __restrict__ dp_f,
            const float* __restrict__ dtw_r, const float* __restrict__ dtb_r,
            const float* __restrict__ alog_r, const float* __restrict__ dp_r)
{
    int lane = threadIdx.x, blk = blockIdx.x;
    int dir = blk >> 7, rem = blk & 127, b = rem >> 4;
    int d = ((rem & 15) << 5) | lane;

    const float* dbl = dir ? g_dblr : g_dblf;
    const float* xc  = dir ? g_xcr  : g_xcf;
    const float* dtw = (dir ? dtw_r : dtw_f) + d*16;
    const float* alg = (dir ? alog_r : alog_f) + d*16;
    float dtb = (dir ? dtb_r : dtb_f)[d];
    float Dpv = (dir ? dp_r  : dp_f )[d];

    float W[16], A[16], h[16];
    bool fast = true;
    #pragma unroll
    for (int n = 0; n < 16; n++) {
        W[n] = dtw[n];
        A[n] = -__expf(alg[n]);
        h[n] = 0.f;
        fast = fast && (fabsf(-A[n] - (float)(n+1)) < 1e-4f*(float)(n+1));
    }

    size_t tbase = (size_t)b*LSEQ;
    const float4* dq  = (const float4*)dbl + tbase*12;
    const float*  xcp = xc + tbase*DI + d;
    const float*  zp  = g_xz + tbase*E2 + DI + d;
    float*        yp  = (dir ? g_yr : g_yf) + tbase*DI + d;

    float qv[48], nv[48];
    #pragma unroll
    for (int q = 0; q < 12; q++) ((float4*)qv)[q] = dq[q];
    float xv = xcp[0];
    float zv = zp[(size_t)(dir ? (LSEQ-1) : 0)*E2];

    for (int l = 0; l < LSEQ; l++) {
        int ln = (l+1 < LSEQ) ? l+1 : l;
        const float4* np = dq + (size_t)ln*12;
        #pragma unroll
        for (int q = 0; q < 12; q++) ((float4*)nv)[q] = np[q];
        float xnv = xcp[(size_t)ln*DI];
        float znv = zp[(size_t)(dir ? (LSEQ-1-ln) : ln)*E2];

        float t0 = dtb, t1 = 0.f, t2 = 0.f, t3 = 0.f;
        #pragma unroll
        for (int k = 0; k < 16; k += 4) {
            t0 = fmaf(qv[k+0], W[k+0], t0); t1 = fmaf(qv[k+1], W[k+1], t1);
            t2 = fmaf(qv[k+2], W[k+2], t2); t3 = fmaf(qv[k+3], W[k+3], t3);
        }
        float dt = (t0+t1) + (t2+t3);
        float ed = __expf(dt);
        float sp = (dt > 15.f) ? dt : __logf(1.f + ed);
        float dtx = sp * xv;
        float y0 = 0.f, y1 = 0.f, y2 = 0.f, y3 = 0.f;
        if (fast) {
            float pw[16];
            pw[0] = __fdividef(1.f, 1.f + ed);   // exp(-softplus(dt))
            #pragma unroll
            for (int n = 1; n < 16; n++) pw[n] = pw[n>>1] * pw[(n-1)>>1]; // p^(n+1)
            #pragma unroll
            for (int n = 0; n < 16; n += 4) {
                h[n+0] = fmaf(pw[n+0], h[n+0], dtx*qv[16+n+0]); y0 = fmaf(h[n+0], qv[32+n+0], y0);
                h[n+1] = fmaf(pw[n+1], h[n+1], dtx*qv[16+n+1]); y1 = fmaf(h[n+1], qv[32+n+1], y1);
                h[n+2] = fmaf(pw[n+2], h[n+2], dtx*qv[16+n+2]); y2 = fmaf(h[n+2], qv[32+n+2], y2);
                h[n+3] = fmaf(pw[n+3], h[n+3], dtx*qv[16+n+3]); y3 = fmaf(h[n+3], qv[32+n+3], y3);
            }
        } else {
            #pragma unroll
            for (int n = 0; n < 16; n++) {
                float e = __expf(sp * A[n]);
                h[n] = fmaf(e, h[n], dtx*qv[16+n]);
                y0 = fmaf(h[n], qv[32+n], y0);
            }
        }
        float y = (y0+y1) + (y2+y3);
        float sz = __fdividef(zv, 1.f + __expf(-zv));
        int sl = dir ? (LSEQ-1-l) : l;
        yp[(size_t)sl*DI] = fmaf(Dpv, xv, y) * sz;
        #pragma unroll
        for (int q = 0; q < 48; q++) qv[q] = nv[q];
        xv = xnv; zv = znv;
    }
}

// ---- generic NT SGEMM: C[m,n] = sum_k A[m,k]*B[n,k]; BM=128 BN=64 BK=16 ----
template<bool DUAL_A, bool HAS_BIAS, bool TRANS_OUT>
__global__ void __launch_bounds__(256, 2)
sgemm_nt(int M, int N, int K,
         const float* __restrict__ A, const float* __restrict__ A2,
         const float* __restrict__ Bw, float* __restrict__ C, int ldc,
         const float* __restrict__ bias)
{
    __shared__ float As[16][132];
    __shared__ float Bs[16][68];
    int tid = threadIdx.x;
    int m0 = blockIdx.x * 128, n0 = blockIdx.y * 64;
    int am = tid >> 2, ak = (tid & 3) << 2;
    const float* Ap  = A + (size_t)(m0 + am)*K + ak;
    const float* Ap2 = A + (size_t)(m0 + am + 64)*K + ak;
    const float* Dq1 = DUAL_A ? (A2 + (size_t)(m0 + am)*K + ak) : A;
    const float* Dq2 = DUAL_A ? (A2 + (size_t)(m0 + am + 64)*K + ak) : A;
    int bn = tid >> 2;
    bool bok = (n0 + bn) < N;
    const float* Bp = Bw + (size_t)(n0 + bn)*K + ak;
    int tx = tid & 15, ty = tid >> 4;
    float acc[8][4];
    #pragma unroll
    for (int i = 0; i < 8; i++)
        #pragma unroll
        for (int j = 0; j < 4; j++) acc[i][j] = 0.f;

    for (int k0 = 0; k0 < K; k0 += 16) {
        float4 a0 = *(const float4*)(Ap  + k0);
        float4 a1 = *(const float4*)(Ap2 + k0);
        if (DUAL_A) {
            float4 c0 = *(const float4*)(Dq1 + k0);
            float4 c1 = *(const float4*)(Dq2 + k0);
            a0.x += c0.x; a0.y += c0.y; a0.z += c0.z; a0.w += c0.w;
            a1.x += c1.x; a1.y += c1.y; a1.z += c1.z; a1.w += c1.w;
        }
        float4 bq = make_float4(0.f,0.f,0.f,0.f);
        if (bok) bq = *(const float4*)(Bp + k0);
        __syncthreads();
        As[ak+0][am] = a0.x; As[ak+1][am] = a0.y; As[ak+2][am] = a0.z; As[ak+3][am] = a0.w;
        As[ak+0][am+64] = a1.x; As[ak+1][am+64] = a1.y; As[ak+2][am+64] = a1.z; As[ak+3][am+64] = a1.w;
        Bs[ak+0][bn] = bq.x; Bs[ak+1][bn] = bq.y; Bs[ak+2][bn] = bq.z; Bs[ak+3][bn] = bq.w;
        __syncthreads();
        #pragma unroll
        for (int kk = 0; kk < 16; kk++) {
            float4 av0 = *(const float4*)&As[kk][ty*8];
            float4 av1 = *(const float4*)&As[kk][ty*8+4];
            float4 bv  = *(const float4*)&Bs[kk][tx*4];
            float a[8] = {av0.x,av0.y,av0.z,av0.w,av1.x,av1.y,av1.z,av1.w};
            float bb[4] = {bv.x,bv.y,bv.z,bv.w};
            #pragma unroll
            for (int i = 0; i < 8; i++)
                #pragma unroll
                for (int j = 0; j < 4; j++)
                    acc[i][j] = fmaf(a[i], bb[j], acc[i][j]);
        }
    }

    if (!TRANS_OUT) {
        int col = n0 + tx*4;
        if (col < N) {
            float4 ba = make_float4(0.f,0.f,0.f,0.f);
            if (HAS_BIAS) { ba.x=bias[col]; ba.y=bias[col+1]; ba.z=bias[col+2]; ba.w=bias[col+3]; }
            #pragma unroll
            for (int i = 0; i < 8; i++) {
                int row = m0 + ty*8 + i;
                float4 v = make_float4(acc[i][0]+ba.x, acc[i][1]+ba.y, acc[i][2]+ba.z, acc[i][3]+ba.w);
                *(float4*)&C[(size_t)row*ldc + col] = v;
            }
        }
    } else {
        // out[b][o][l], l = token & 4095
        #pragma unroll
        for (int i = 0; i < 8; i++) {
            int t = m0 + ty*8 + i;
            int bo = t >> 12, l = t & 4095;
            #pragma unroll
            for (int j = 0; j < 4; j++) {
                int o = n0 + tx*4 + j;
                float v = acc[i][j];
                if (HAS_BIAS) v += bias[o];
                C[((size_t)bo*N + o)*LSEQ + l] = v;
            }
        }
    }
}

extern "C" void kernel_launch(void* const* d_in, const int* in_sizes, int n_in,
                              void* d_out, int out_size)
{
    const float* x       = (const float*)d_in[0];
    const float* norm_g  = (const float*)d_in[1];
    const float* norm_b  = (const float*)d_in[2];
    const float* skip    = (const float*)d_in[3];
    const float* proj_w  = (const float*)d_in[4];
    const float* proj_b  = (const float*)d_in[5];
    const float* in_w    = (const float*)d_in[6];
    const float* out_w   = (const float*)d_in[7];
    const float* cwf     = (const float*)d_in[8];
    const float* cbf     = (const float*)d_in[9];
    const float* xpw_f   = (const float*)d_in[10];
    const float* dtw_f   = (const float*)d_in[11];
    const float* dtb_f   = (const float*)d_in[12];
    const float* alog_f  = (const float*)d_in[13];
    const float* dp_f    = (const float*)d_in[14];
    const float* cwr     = (const float*)d_in[15];
    const float* cbr     = (const float*)d_in[16];
    const float* xpw_r   = (const float*)d_in[17];
    const float* dtw_r   = (const float*)d_in[18];
    const float* dtb_r   = (const float*)d_in[19];
    const float* alog_r  = (const float*)d_in[20];
    const float* dp_r    = (const float*)d_in[21];
    float* out = (float*)d_out;

    float *p_xn, *p_xz, *p_xcf, *p_xcr, *p_dblf, *p_dblr, *p_yf, *p_yr, *p_mo, *p_xmn;
    cudaGetSymbolAddress((void**)&p_xn,  g_xn);
    cudaGetSymbolAddress((void**)&p_xz,  g_xz);
    cudaGetSymbolAddress((void**)&p_xcf, g_xcf);
    cudaGetSymbolAddress((void**)&p_xcr, g_xcr);
    cudaGetSymbolAddress((void**)&p_dblf,g_dblf);
    cudaGetSymbolAddress((void**)&p_dblr,g_dblr);
    cudaGetSymbolAddress((void**)&p_yf,  g_yf);
    cudaGetSymbolAddress((void**)&p_yr,  g_yr);
    cudaGetSymbolAddress((void**)&p_mo,  g_mo);
    cudaGetSymbolAddress((void**)&p_xmn, g_xmn);

    dim3 lng(LSEQ/32, BB);
    ln_kernel<false><<<lng, 256>>>(x, norm_g, norm_b, skip, p_xn);

    sgemm_nt<false,false,false><<<dim3(NTOK/128, E2/64), 256>>>(
        NTOK, E2, CDIM, p_xn, nullptr, in_w, p_xz, E2, nullptr);

    conv_kernel<<<(2*NTOK*DI)/256, 256>>>(cwf, cbf, cwr, cbr);

    sgemm_nt<false,false,false><<<dim3(NTOK/128, 1), 256>>>(
        NTOK, 48, DI, p_xcf, nullptr, xpw_f, p_dblf, 48, nullptr);
    sgemm_nt<false,false,false><<<dim3(NTOK/128, 1), 256>>>(
        NTOK, 48, DI, p_xcr, nullptr, xpw_r, p_dblr, 48, nullptr);

    scan_kernel<<<256, 32>>>(dtw_f, dtb_f, alog_f, dp_f, dtw_r, dtb_r, alog_r, dp_r);

    sgemm_nt<true,false,false><<<dim3(NTOK/128, CDIM/64), 256>>>(
        NTOK, CDIM, DI, p_yf, p_yr, out_w, p_mo, CDIM, nullptr);

    ln_kernel<true><<<lng, 256>>>(x, norm_g, norm_b, skip, p_xmn);

    sgemm_nt<false,true,true><<<dim3(NTOK/128, CDIM/64), 256>>>(
        NTOK, CDIM, CDIM, p_xmn, nullptr, proj_w, out, CDIM, proj_b);
}

// round 10
// speedup vs baseline: 2.0994x; 2.0994x over previous
#include <cuda_runtime.h>

#define BB   8
#define LSEQ 4096
#define CDIM 256
#define DI   512
#define E2   1024
#define NTOK (BB*LSEQ)
#define CH   128
#define NCH  32

__device__ float g_xn  [NTOK*CDIM];
__device__ float g_xz  [(size_t)NTOK*E2];
__device__ float g_xcf [NTOK*DI];
__device__ float g_xcr [NTOK*DI];
__device__ float g_dblf[NTOK*48];
__device__ float g_dblr[NTOK*48];
__device__ float g_yf  [NTOK*DI];
__device__ float g_yr  [NTOK*DI];
__device__ float g_mo  [NTOK*CDIM];
__device__ float g_xmn [NTOK*CDIM];
// chunked-scan intermediates: [dir*8+b][chunk][n][d] and [dir*8+b][chunk][d]
__device__ float g_hout[2*8*NCH*16*DI];
__device__ float g_hin [2*8*NCH*16*DI];
__device__ float g_S   [2*8*NCH*DI];

// ---- LayerNorm over c of x[b,c,l] (+optional mo[b,l,c] + skip) -> out[b,l,c] ----
template<bool ADD_MO>
__global__ void ln_kernel(const float* __restrict__ x,
                          const float* __restrict__ g,
                          const float* __restrict__ be,
                          const float* __restrict__ skip,
                          float* __restrict__ out)
{
    __shared__ float sm[256][33];
    __shared__ float smean[32], srstd[32];
    int l0 = blockIdx.x * 32, b = blockIdx.y, tid = threadIdx.x;
    const float* xb = x + (size_t)b*CDIM*LSEQ;
    #pragma unroll
    for (int i = 0; i < 32; i++) {
        int idx = tid + i*256, c = idx >> 5, li = idx & 31;
        sm[c][li] = xb[(size_t)c*LSEQ + l0 + li];
    }
    __syncthreads();
    float sk = ADD_MO ? skip[0] : 0.f;
    const float* mo = g_mo + ((size_t)b*LSEQ + l0)*CDIM;
    int w = tid >> 5, lane = tid & 31;
    for (int li = w; li < 32; li += 8) {
        float s = 0.f, s2 = 0.f;
        #pragma unroll
        for (int j = 0; j < 8; j++) {
            int c = lane + (j << 5);
            float v = sm[c][li];
            if (ADD_MO) { v = fmaf(sk, v, mo[(size_t)li*CDIM + c]); sm[c][li] = v; }
            s += v; s2 += v*v;
        }
        #pragma unroll
        for (int off = 16; off; off >>= 1) {
            s  += __shfl_xor_sync(0xffffffffu, s,  off);
            s2 += __shfl_xor_sync(0xffffffffu, s2, off);
        }
        if (lane == 0) {
            float m = s * (1.f/256.f);
            smean[li] = m;
            srstd[li] = rsqrtf(s2*(1.f/256.f) - m*m + 1e-5f);
        }
    }
    __syncthreads();
    float* op = out + ((size_t)b*LSEQ + l0)*CDIM;
    #pragma unroll
    for (int i = 0; i < 32; i++) {
        int idx = tid + i*256, li = idx >> 8, c = idx & 255;
        op[(size_t)li*CDIM + c] = (sm[c][li] - smean[li])*srstd[li]*g[c] + be[c];
    }
}

// ---- causal depthwise conv + SiLU, both directions ----
__global__ void conv_kernel(const float* __restrict__ cwf, const float* __restrict__ cbf,
                            const float* __restrict__ cwr, const float* __restrict__ cbr)
{
    int idx = blockIdx.x*256 + threadIdx.x;
    int d = idx & (DI-1), l = (idx >> 9) & (LSEQ-1), b = (idx >> 21) & 7, dir = idx >> 24;
    const float* w = (dir ? cwr : cwf) + d*4;
    float acc = (dir ? cbr : cbf)[d];
    const float* xzb = g_xz + (size_t)b*LSEQ*E2 + d;
    #pragma unroll
    for (int j = 0; j < 4; j++) {
        int ir = l - 3 + j;
        if (ir >= 0) {
            int ls = dir ? (LSEQ-1-ir) : ir;
            acc = fmaf(w[j], xzb[(size_t)ls*E2], acc);
        }
    }
    float s = __fdividef(acc, 1.f + __expf(-acc));
    (dir ? g_xcr : g_xcf)[((size_t)b*LSEQ + l)*DI + d] = s;
}

// ================= chunk-parallel selective scan =================
// Phase 1: local scan of CH steps from h=0; emit h_out[16] and S = sum(softplus)
__global__ void __launch_bounds__(256)
scan_p1(const float* __restrict__ dtw_f, const float* __restrict__ dtb_f,
        const float* __restrict__ alog_f,
        const float* __restrict__ dtw_r, const float* __restrict__ dtb_r,
        const float* __restrict__ alog_r)
{
    int tid = threadIdx.x;
    int chunk = blockIdx.x >> 1;
    int d = ((blockIdx.x & 1) << 8) | tid;
    int b = blockIdx.y, dir = blockIdx.z;

    const float* dbl = dir ? g_dblr : g_dblf;
    const float* xc  = dir ? g_xcr  : g_xcf;
    const float* dtw = (dir ? dtw_r : dtw_f) + d*16;
    const float* alg = (dir ? alog_r : alog_f) + d*16;
    float dtb = (dir ? dtb_r : dtb_f)[d];

    float W[16], A[16], h[16];
    bool fast = true;
    #pragma unroll
    for (int n = 0; n < 16; n++) {
        W[n] = dtw[n];
        A[n] = -__expf(alg[n]);
        h[n] = 0.f;
        fast = fast && (fabsf(-A[n] - (float)(n+1)) < 1e-4f*(float)(n+1));
    }

    size_t t0 = (size_t)b*LSEQ + (size_t)chunk*CH;
    const float4* dq = (const float4*)dbl + t0*12;
    const float*  xcp = xc + t0*DI + d;
    float S = 0.f;

    if (fast) {
        for (int l = 0; l < CH; l++) {
            float q[32];
            #pragma unroll
            for (int i = 0; i < 8; i++) ((float4*)q)[i] = dq[(size_t)l*12 + i];
            float xv = xcp[(size_t)l*DI];
            float a0 = dtb, a1 = 0.f, a2 = 0.f, a3 = 0.f;
            #pragma unroll
            for (int k = 0; k < 16; k += 4) {
                a0 = fmaf(q[k+0], W[k+0], a0); a1 = fmaf(q[k+1], W[k+1], a1);
                a2 = fmaf(q[k+2], W[k+2], a2); a3 = fmaf(q[k+3], W[k+3], a3);
            }
            float dt = (a0+a1)+(a2+a3);
            float ed = __expf(dt);
            float sp = (dt > 15.f) ? dt : __logf(1.f + ed);
            S += sp;
            float dtx = sp * xv;
            float pw[16];
            pw[0] = __fdividef(1.f, 1.f + ed);
            #pragma unroll
            for (int n = 1; n < 16; n++) pw[n] = pw[n>>1] * pw[(n-1)>>1];
            #pragma unroll
            for (int n = 0; n < 16; n++) h[n] = fmaf(pw[n], h[n], dtx*q[16+n]);
        }
    } else {
        for (int l = 0; l < CH; l++) {
            float q[32];
            #pragma unroll
            for (int i = 0; i < 8; i++) ((float4*)q)[i] = dq[(size_t)l*12 + i];
            float xv = xcp[(size_t)l*DI];
            float a0 = dtb, a1 = 0.f, a2 = 0.f, a3 = 0.f;
            #pragma unroll
            for (int k = 0; k < 16; k += 4) {
                a0 = fmaf(q[k+0], W[k+0], a0); a1 = fmaf(q[k+1], W[k+1], a1);
                a2 = fmaf(q[k+2], W[k+2], a2); a3 = fmaf(q[k+3], W[k+3], a3);
            }
            float dt = (a0+a1)+(a2+a3);
            float ed = __expf(dt);
            float sp = (dt > 15.f) ? dt : __logf(1.f + ed);
            S += sp;
            float dtx = sp * xv;
            #pragma unroll
            for (int n = 0; n < 16; n++)
                h[n] = fmaf(__expf(sp*A[n]), h[n], dtx*q[16+n]);
        }
    }
    size_t base = (size_t)((dir*8 + b)*NCH + chunk);
    #pragma unroll
    for (int n = 0; n < 16; n++) g_hout[(base*16 + n)*DI + d] = h[n];
    g_S[base*DI + d] = S;
}

// Phase 2: sequential combine over chunks -> h_in per chunk
__global__ void __launch_bounds__(256)
scan_p2(const float* __restrict__ alog_f, const float* __restrict__ alog_r)
{
    int t = blockIdx.x*256 + threadIdx.x;   // 8192 threads
    int dir = t >> 12, b = (t >> 9) & 7, d = t & 511;
    const float* alg = (dir ? alog_r : alog_f) + d*16;
    float A[16], H[16];
    bool fast = true;
    #pragma unroll
    for (int n = 0; n < 16; n++) {
        A[n] = -__expf(alg[n]);
        H[n] = 0.f;
        fast = fast && (fabsf(-A[n] - (float)(n+1)) < 1e-4f*(float)(n+1));
    }
    size_t dirb = (size_t)(dir*8 + b);
    for (int c = 0; c < NCH; c++) {
        size_t base = dirb*NCH + c;
        #pragma unroll
        for (int n = 0; n < 16; n++) g_hin[(base*16 + n)*DI + d] = H[n];
        float S = g_S[base*DI + d];
        if (fast) {
            float pw[16];
            pw[0] = __expf(-S);
            #pragma unroll
            for (int n = 1; n < 16; n++) pw[n] = pw[n>>1] * pw[(n-1)>>1];
            #pragma unroll
            for (int n = 0; n < 16; n++)
                H[n] = fmaf(pw[n], H[n], g_hout[(base*16 + n)*DI + d]);
        } else {
            #pragma unroll
            for (int n = 0; n < 16; n++)
                H[n] = fmaf(__expf(A[n]*S), H[n], g_hout[(base*16 + n)*DI + d]);
        }
    }
}

// Phase 3: rescan from h_in, produce y = (scan + Dp*x) * silu(z)
__global__ void __launch_bounds__(256)
scan_p3(const float* __restrict__ dtw_f, const float* __restrict__ dtb_f,
        const float* __restrict__ alog_f, const float* __restrict__ dp_f,
        const float* __restrict__ dtw_r, const float* __restrict__ dtb_r,
        const float* __restrict__ alog_r, const float* __restrict__ dp_r)
{
    int tid = threadIdx.x;
    int chunk = blockIdx.x >> 1;
    int d = ((blockIdx.x & 1) << 8) | tid;
    int b = blockIdx.y, dir = blockIdx.z;

    const float* dbl = dir ? g_dblr : g_dblf;
    const float* xc  = dir ? g_xcr  : g_xcf;
    const float* dtw = (dir ? dtw_r : dtw_f) + d*16;
    const float* alg = (dir ? alog_r : alog_f) + d*16;
    float dtb = (dir ? dtb_r : dtb_f)[d];
    float Dpv = (dir ? dp_r  : dp_f )[d];

    float W[16], A[16], h[16];
    bool fast = true;
    size_t base = (size_t)((dir*8 + b)*NCH + chunk);
    #pragma unroll
    for (int n = 0; n < 16; n++) {
        W[n] = dtw[n];
        A[n] = -__expf(alg[n]);
        h[n] = g_hin[(base*16 + n)*DI + d];
        fast = fast && (fabsf(-A[n] - (float)(n+1)) < 1e-4f*(float)(n+1));
    }

    size_t t0 = (size_t)b*LSEQ + (size_t)chunk*CH;
    const float4* dq = (const float4*)dbl + t0*12;
    const float*  xcp = xc + t0*DI + d;
    const float*  zb  = g_xz + (size_t)b*LSEQ*E2 + DI + d;
    float* yp = (dir ? g_yr : g_yf) + (size_t)b*LSEQ*DI + d;

    for (int l = 0; l < CH; l++) {
        float q[48];
        #pragma unroll
        for (int i = 0; i < 12; i++) ((float4*)q)[i] = dq[(size_t)l*12 + i];
        float xv = xcp[(size_t)l*DI];
        int lf = chunk*CH + l;
        int zl = dir ? (LSEQ-1-lf) : lf;
        float zv = zb[(size_t)zl*E2];

        float a0 = dtb, a1 = 0.f, a2 = 0.f, a3 = 0.f;
        #pragma unroll
        for (int k = 0; k < 16; k += 4) {
            a0 = fmaf(q[k+0], W[k+0], a0); a1 = fmaf(q[k+1], W[k+1], a1);
            a2 = fmaf(q[k+2], W[k+2], a2); a3 = fmaf(q[k+3], W[k+3], a3);
        }
        float dt = (a0+a1)+(a2+a3);
        float ed = __expf(dt);
        float sp = (dt > 15.f) ? dt : __logf(1.f + ed);
        float dtx = sp * xv;
        float y0 = 0.f, y1 = 0.f, y2 = 0.f, y3 = 0.f;
        if (fast) {
            float pw[16];
            pw[0] = __fdividef(1.f, 1.f + ed);
            #pragma unroll
            for (int n = 1; n < 16; n++) pw[n] = pw[n>>1] * pw[(n-1)>>1];
            #pragma unroll
            for (int n = 0; n < 16; n += 4) {
                h[n+0] = fmaf(pw[n+0], h[n+0], dtx*q[16+n+0]); y0 = fmaf(h[n+0], q[32+n+0], y0);
                h[n+1] = fmaf(pw[n+1], h[n+1], dtx*q[16+n+1]); y1 = fmaf(h[n+1], q[32+n+1], y1);
                h[n+2] = fmaf(pw[n+2], h[n+2], dtx*q[16+n+2]); y2 = fmaf(h[n+2], q[32+n+2], y2);
                h[n+3] = fmaf(pw[n+3], h[n+3], dtx*q[16+n+3]); y3 = fmaf(h[n+3], q[32+n+3], y3);
            }
        } else {
            #pragma unroll
            for (int n = 0; n < 16; n++) {
                h[n] = fmaf(__expf(sp*A[n]), h[n], dtx*q[16+n]);
                y0 = fmaf(h[n], q[32+n], y0);
            }
        }
        float y = (y0+y1)+(y2+y3);
        float sz = __fdividef(zv, 1.f + __expf(-zv));
        int sl = dir ? (LSEQ-1-lf) : lf;
        yp[(size_t)sl*DI] = fmaf(Dpv, xv, y) * sz;
    }
}

// ---- generic NT SGEMM: C[m,n] = sum_k A[m,k]*B[n,k]; BM=128 BN=64 BK=16 ----
template<bool DUAL_A, bool HAS_BIAS, bool TRANS_OUT>
__global__ void __launch_bounds__(256, 2)
sgemm_nt(int M, int N, int K,
         const float* __restrict__ A, const float* __restrict__ A2,
         const float* __restrict__ Bw, float* __restrict__ C, int ldc,
         const float* __restrict__ bias)
{
    __shared__ float As[16][132];
    __shared__ float Bs[16][68];
    int tid = threadIdx.x;
    int m0 = blockIdx.x * 128, n0 = blockIdx.y * 64;
    int am = tid >> 2, ak = (tid & 3) << 2;
    const float* Ap  = A + (size_t)(m0 + am)*K + ak;
    const float* Ap2 = A + (size_t)(m0 + am + 64)*K + ak;
    const float* Dq1 = DUAL_A ? (A2 + (size_t)(m0 + am)*K + ak) : A;
    const float* Dq2 = DUAL_A ? (A2 + (size_t)(m0 + am + 64)*K + ak) : A;
    int bn = tid >> 2;
    bool bok = (n0 + bn) < N;
    const float* Bp = Bw + (size_t)(n0 + bn)*K + ak;
    int tx = tid & 15, ty = tid >> 4;
    float acc[8][4];
    #pragma unroll
    for (int i = 0; i < 8; i++)
        #pragma unroll
        for (int j = 0; j < 4; j++) acc[i][j] = 0.f;

    for (int k0 = 0; k0 < K; k0 += 16) {
        float4 a0 = *(const float4*)(Ap  + k0);
        float4 a1 = *(const float4*)(Ap2 + k0);
        if (DUAL_A) {
            float4 c0 = *(const float4*)(Dq1 + k0);
            float4 c1 = *(const float4*)(Dq2 + k0);
            a0.x += c0.x; a0.y += c0.y; a0.z += c0.z; a0.w += c0.w;
            a1.x += c1.x; a1.y += c1.y; a1.z += c1.z; a1.w += c1.w;
        }
        float4 bq = make_float4(0.f,0.f,0.f,0.f);
        if (bok) bq = *(const float4*)(Bp + k0);
        __syncthreads();
        As[ak+0][am] = a0.x; As[ak+1][am] = a0.y; As[ak+2][am] = a0.z; As[ak+3][am] = a0.w;
        As[ak+0][am+64] = a1.x; As[ak+1][am+64] = a1.y; As[ak+2][am+64] = a1.z; As[ak+3][am+64] = a1.w;
        Bs[ak+0][bn] = bq.x; Bs[ak+1][bn] = bq.y; Bs[ak+2][bn] = bq.z; Bs[ak+3][bn] = bq.w;
        __syncthreads();
        #pragma unroll
        for (int kk = 0; kk < 16; kk++) {
            float4 av0 = *(const float4*)&As[kk][ty*8];
            float4 av1 = *(const float4*)&As[kk][ty*8+4];
            float4 bv  = *(const float4*)&Bs[kk][tx*4];
            float a[8] = {av0.x,av0.y,av0.z,av0.w,av1.x,av1.y,av1.z,av1.w};
            float bb[4] = {bv.x,bv.y,bv.z,bv.w};
            #pragma unroll
            for (int i = 0; i < 8; i++)
                #pragma unroll
                for (int j = 0; j < 4; j++)
                    acc[i][j] = fmaf(a[i], bb[j], acc[i][j]);
        }
    }

    if (!TRANS_OUT) {
        int col = n0 + tx*4;
        if (col < N) {
            float4 ba = make_float4(0.f,0.f,0.f,0.f);
            if (HAS_BIAS) { ba.x=bias[col]; ba.y=bias[col+1]; ba.z=bias[col+2]; ba.w=bias[col+3]; }
            #pragma unroll
            for (int i = 0; i < 8; i++) {
                int row = m0 + ty*8 + i;
                float4 v = make_float4(acc[i][0]+ba.x, acc[i][1]+ba.y, acc[i][2]+ba.z, acc[i][3]+ba.w);
                *(float4*)&C[(size_t)row*ldc + col] = v;
            }
        }
    } else {
        #pragma unroll
        for (int i = 0; i < 8; i++) {
            int t = m0 + ty*8 + i;
            int bo = t >> 12, l = t & 4095;
            #pragma unroll
            for (int j = 0; j < 4; j++) {
                int o = n0 + tx*4 + j;
                float v = acc[i][j];
                if (HAS_BIAS) v += bias[o];
                C[((size_t)bo*N + o)*LSEQ + l] = v;
            }
        }
    }
}

extern "C" void kernel_launch(void* const* d_in, const int* in_sizes, int n_in,
                              void* d_out, int out_size)
{
    const float* x       = (const float*)d_in[0];
    const float* norm_g  = (const float*)d_in[1];
    const float* norm_b  = (const float*)d_in[2];
    const float* skip    = (const float*)d_in[3];
    const float* proj_w  = (const float*)d_in[4];
    const float* proj_b  = (const float*)d_in[5];
    const float* in_w    = (const float*)d_in[6];
    const float* out_w   = (const float*)d_in[7];
    const float* cwf     = (const float*)d_in[8];
    const float* cbf     = (const float*)d_in[9];
    const float* xpw_f   = (const float*)d_in[10];
    const float* dtw_f   = (const float*)d_in[11];
    const float* dtb_f   = (const float*)d_in[12];
    const float* alog_f  = (const float*)d_in[13];
    const float* dp_f    = (const float*)d_in[14];
    const float* cwr     = (const float*)d_in[15];
    const float* cbr     = (const float*)d_in[16];
    const float* xpw_r   = (const float*)d_in[17];
    const float* dtw_r   = (const float*)d_in[18];
    const float* dtb_r   = (const float*)d_in[19];
    const float* alog_r  = (const float*)d_in[20];
    const float* dp_r    = (const float*)d_in[21];
    float* out = (float*)d_out;

    float *p_xn, *p_xz, *p_xcf, *p_xcr, *p_dblf, *p_dblr, *p_yf, *p_yr, *p_mo, *p_xmn;
    cudaGetSymbolAddress((void**)&p_xn,  g_xn);
    cudaGetSymbolAddress((void**)&p_xz,  g_xz);
    cudaGetSymbolAddress((void**)&p_xcf, g_xcf);
    cudaGetSymbolAddress((void**)&p_xcr, g_xcr);
    cudaGetSymbolAddress((void**)&p_dblf,g_dblf);
    cudaGetSymbolAddress((void**)&p_dblr,g_dblr);
    cudaGetSymbolAddress((void**)&p_yf,  g_yf);
    cudaGetSymbolAddress((void**)&p_yr,  g_yr);
    cudaGetSymbolAddress((void**)&p_mo,  g_mo);
    cudaGetSymbolAddress((void**)&p_xmn, g_xmn);

    dim3 lng(LSEQ/32, BB);
    ln_kernel<false><<<lng, 256>>>(x, norm_g, norm_b, skip, p_xn);

    sgemm_nt<false,false,false><<<dim3(NTOK/128, E2/64), 256>>>(
        NTOK, E2, CDIM, p_xn, nullptr, in_w, p_xz, E2, nullptr);

    conv_kernel<<<(2*NTOK*DI)/256, 256>>>(cwf, cbf, cwr, cbr);

    sgemm_nt<false,false,false><<<dim3(NTOK/128, 1), 256>>>(
        NTOK, 48, DI, p_xcf, nullptr, xpw_f, p_dblf, 48, nullptr);
    sgemm_nt<false,false,false><<<dim3(NTOK/128, 1), 256>>>(
        NTOK, 48, DI, p_xcr, nullptr, xpw_r, p_dblr, 48, nullptr);

    dim3 sg(2*NCH, BB, 2);
    scan_p1<<<sg, 256>>>(dtw_f, dtb_f, alog_f, dtw_r, dtb_r, alog_r);
    scan_p2<<<32, 256>>>(alog_f, alog_r);
    scan_p3<<<sg, 256>>>(dtw_f, dtb_f, alog_f, dp_f, dtw_r, dtb_r, alog_r, dp_r);

    sgemm_nt<true,false,false><<<dim3(NTOK/128, CDIM/64), 256>>>(
        NTOK, CDIM, DI, p_yf, p_yr, out_w, p_mo, CDIM, nullptr);

    ln_kernel<true><<<lng, 256>>>(x, norm_g, norm_b, skip, p_xmn);

    sgemm_nt<false,true,true><<<dim3(NTOK/128, CDIM/64), 256>>>(
        NTOK, CDIM, CDIM, p_xmn, nullptr, proj_w, out, CDIM, proj_b);
}

// round 13
// speedup vs baseline: 2.2380x; 1.0660x over previous
#include <cuda_runtime.h>
#include <cuda_bf16.h>
#include <cstdint>

#define BB   8
#define LSEQ 4096
#define CDIM 256
#define DI   512
#define E2   1024
#define NTOK (BB*LSEQ)
#define CH   128
#define NCH  32

// fp32 scratch
__device__ float g_xz  [(size_t)NTOK*E2];
__device__ float g_xcf [NTOK*DI];
__device__ float g_xcr [NTOK*DI];
__device__ float g_dblf[NTOK*48];
__device__ float g_dblr[NTOK*48];
__device__ float g_yf  [NTOK*DI];
__device__ float g_yr  [NTOK*DI];
__device__ float g_mo  [NTOK*CDIM];
__device__ float g_hout[2*8*NCH*16*DI];
__device__ float g_hin [2*8*NCH*16*DI];
__device__ float g_S   [2*8*NCH*DI];
// bf16 split planes (hi, lo)
__device__ __nv_bfloat16 g_xnh [NTOK*CDIM],  g_xnl [NTOK*CDIM];
__device__ __nv_bfloat16 g_xcfh[NTOK*DI],    g_xcfl[NTOK*DI];
__device__ __nv_bfloat16 g_xcrh[NTOK*DI],    g_xcrl[NTOK*DI];
__device__ __nv_bfloat16 g_ysh [NTOK*DI],    g_ysl [NTOK*DI];
__device__ __nv_bfloat16 g_xmnh[NTOK*CDIM],  g_xmnl[NTOK*CDIM];
__device__ __nv_bfloat16 g_inwh[E2*CDIM],    g_inwl[E2*CDIM];
__device__ __nv_bfloat16 g_owh [CDIM*DI],    g_owl [CDIM*DI];
__device__ __nv_bfloat16 g_pwh [CDIM*CDIM],  g_pwl [CDIM*CDIM];
__device__ __nv_bfloat16 g_xpfh[48*DI],      g_xpfl[48*DI];
__device__ __nv_bfloat16 g_xprh[48*DI],      g_xprl[48*DI];

// ================= bf16 mma.sync GEMM over virtual K' = 3K =================
// C[m,n] = Ah·Bh + Al·Bh + Ah·Bl  (each plane bf16, fp32 accumulate)
// Block tile 128x64, BK=32, 256 threads = 8 warps (4x2), warp tile 32x32.
#define SAS 40   // smem row stride in bf16 elems (80B) — conflict-free frag loads

__device__ __forceinline__ void mma16816(float* d, const uint32_t* a, const uint32_t* b) {
    asm volatile(
        "mma.sync.aligned.m16n8k16.row.col.f32.bf16.bf16.f32 "
        "{%0,%1,%2,%3}, {%4,%5,%6,%7}, {%8,%9}, {%0,%1,%2,%3};"
        : "+f"(d[0]), "+f"(d[1]), "+f"(d[2]), "+f"(d[3])
        : "r"(a[0]), "r"(a[1]), "r"(a[2]), "r"(a[3]), "r"(b[0]), "r"(b[1]));
}

template<bool HAS_BIAS, bool TRANS_OUT>
__global__ void __launch_bounds__(256)
gemm_mma(int K, const __nv_bfloat16* __restrict__ Ah, const __nv_bfloat16* __restrict__ Al,
         const __nv_bfloat16* __restrict__ Bh, const __nv_bfloat16* __restrict__ Bl,
         float* __restrict__ C, int ldc, int Nact, const float* __restrict__ bias)
{
    __shared__ __align__(16) __nv_bfloat16 As[128*SAS];
    __shared__ __align__(16) __nv_bfloat16 Bs[64*SAS];

    int tid = threadIdx.x;
    int m0 = blockIdx.x * 128, n0 = blockIdx.y * 64;

    // loader indices
    int lrow  = tid >> 1;             // 0..127 (A row)
    int lhalf = (tid & 1) << 4;       // 0 | 16 elems
    int brow  = tid >> 2;             // 0..63 (B row)
    int bseg  = (tid & 3) << 3;       // 0,8,16,24 elems
    bool bok  = (n0 + brow) < Nact;

    // warp/frag indices
    int wid = tid >> 5, lane = tid & 31;
    int wm = (wid & 3) << 5;          // 0,32,64,96
    int wn = (wid >> 2) << 5;         // 0,32
    int r4 = lane >> 2, c2 = (lane & 3) << 1;

    float acc[2][4][4];
    #pragma unroll
    for (int i = 0; i < 2; i++)
        #pragma unroll
        for (int j = 0; j < 4; j++)
            #pragma unroll
            for (int q = 0; q < 4; q++) acc[i][j][q] = 0.f;

    int niter = (3*K) >> 5;
    uint4 ra0, ra1, rb;

    // prologue global load (iter 0, segment 0 => Ah, Bh)
    {
        const __nv_bfloat16* Ap = Ah + (size_t)(m0 + lrow)*K + lhalf;
        ra0 = *(const uint4*)Ap;
        ra1 = *(const uint4*)(Ap + 8);
        rb = make_uint4(0,0,0,0);
        if (bok) rb = *(const uint4*)(Bh + (size_t)(n0 + brow)*K + bseg);
    }

    for (int it = 0; it < niter; it++) {
        __syncthreads();
        *(uint4*)&As[lrow*SAS + lhalf]     = ra0;
        *(uint4*)&As[lrow*SAS + lhalf + 8] = ra1;
        *(uint4*)&Bs[brow*SAS + bseg]      = rb;
        __syncthreads();

        if (it + 1 < niter) {
            int ks = (it + 1) << 5;
            int seg = (ks >= 2*K) ? 2 : (ks >= K ? 1 : 0);
            int kk = ks - seg*K;
            const __nv_bfloat16* Apl = (seg == 1) ? Al : Ah;
            const __nv_bfloat16* Bpl = (seg == 2) ? Bl : Bh;
            const __nv_bfloat16* Ap = Apl + (size_t)(m0 + lrow)*K + kk + lhalf;
            ra0 = *(const uint4*)Ap;
            ra1 = *(const uint4*)(Ap + 8);
            rb = make_uint4(0,0,0,0);
            if (bok) rb = *(const uint4*)(Bpl + (size_t)(n0 + brow)*K + kk + bseg);
        }

        #pragma unroll
        for (int k16 = 0; k16 < 32; k16 += 16) {
            uint32_t af[2][4];
            #pragma unroll
            for (int im = 0; im < 2; im++) {
                int base = (wm + im*16 + r4)*SAS + k16 + c2;
                af[im][0] = *(const uint32_t*)&As[base];
                af[im][1] = *(const uint32_t*)&As[base + 8*SAS];
                af[im][2] = *(const uint32_t*)&As[base + 8];
                af[im][3] = *(const uint32_t*)&As[base + 8*SAS + 8];
            }
            uint32_t bf[4][2];
            #pragma unroll
            for (int jn = 0; jn < 4; jn++) {
                int base = (wn + jn*8 + r4)*SAS + k16 + c2;
                bf[jn][0] = *(const uint32_t*)&Bs[base];
                bf[jn][1] = *(const uint32_t*)&Bs[base + 8];
            }
            #pragma unroll
            for (int im = 0; im < 2; im++)
                #pragma unroll
                for (int jn = 0; jn < 4; jn++)
                    mma16816(acc[im][jn], af[im], bf[jn]);
        }
    }

    // epilogue
    #pragma unroll
    for (int im = 0; im < 2; im++) {
        int r = m0 + wm + im*16 + r4;
        #pragma unroll
        for (int jn = 0; jn < 4; jn++) {
            int cN = wn + jn*8 + c2;             // 0..63
            int gc = n0 + cN;
            if (gc + 1 < Nact + 1 && gc < Nact) {
                float b0 = HAS_BIAS ? bias[gc]   : 0.f;
                float b1 = HAS_BIAS ? bias[gc+1] : 0.f;
                if (!TRANS_OUT) {
                    C[(size_t)r*ldc + gc]       = acc[im][jn][0] + b0;
                    C[(size_t)r*ldc + gc + 1]   = acc[im][jn][1] + b1;
                    C[(size_t)(r+8)*ldc + gc]   = acc[im][jn][2] + b0;
                    C[(size_t)(r+8)*ldc + gc+1] = acc[im][jn][3] + b1;
                } else {
                    int t0 = r, t1 = r + 8;
                    int bo0 = t0 >> 12, l0 = t0 & 4095;
                    int bo1 = t1 >> 12, l1 = t1 & 4095;
                    C[((size_t)bo0*ldc + gc)*LSEQ + l0]     = acc[im][jn][0] + b0;
                    C[((size_t)bo0*ldc + gc + 1)*LSEQ + l0] = acc[im][jn][1] + b1;
                    C[((size_t)bo1*ldc + gc)*LSEQ + l1]     = acc[im][jn][2] + b0;
                    C[((size_t)bo1*ldc + gc + 1)*LSEQ + l1] = acc[im][jn][3] + b1;
                }
            }
        }
    }
}

// ================= split helpers =================
__global__ void split_kernel(const float* __restrict__ s, __nv_bfloat16* __restrict__ h,
                             __nv_bfloat16* __restrict__ lo, int n)
{
    int i = blockIdx.x*256 + threadIdx.x;
    if (i < n) {
        float v = s[i];
        __nv_bfloat16 hb = __float2bfloat16(v);
        h[i] = hb;
        lo[i] = __float2bfloat16(v - __bfloat162float(hb));
    }
}
__global__ void ysum_split(const float* __restrict__ a, const float* __restrict__ b,
                           __nv_bfloat16* __restrict__ h, __nv_bfloat16* __restrict__ lo)
{
    int i = blockIdx.x*256 + threadIdx.x;
    float v = a[i] + b[i];
    __nv_bfloat16 hb = __float2bfloat16(v);
    h[i] = hb;
    lo[i] = __float2bfloat16(v - __bfloat162float(hb));
}

// ---- LayerNorm over c of x[b,c,l] (+optional mo + skip) -> bf16 hi/lo [b,l,c] ----
template<bool ADD_MO>
__global__ void ln_kernel(const float* __restrict__ x,
                          const float* __restrict__ g,
                          const float* __restrict__ be,
                          const float* __restrict__ skip,
                          __nv_bfloat16* __restrict__ oh,
                          __nv_bfloat16* __restrict__ ol)
{
    __shared__ float sm[256][33];
    __shared__ float smean[32], srstd[32];
    int l0 = blockIdx.x * 32, b = blockIdx.y, tid = threadIdx.x;
    const float* xb = x + (size_t)b*CDIM*LSEQ;
    #pragma unroll
    for (int i = 0; i < 32; i++) {
        int idx = tid + i*256, c = idx >> 5, li = idx & 31;
        sm[c][li] = xb[(size_t)c*LSEQ + l0 + li];
    }
    __syncthreads();
    float sk = ADD_MO ? skip[0] : 0.f;
    const float* mo = g_mo + ((size_t)b*LSEQ + l0)*CDIM;
    int w = tid >> 5, lane = tid & 31;
    for (int li = w; li < 32; li += 8) {
        float s = 0.f, s2 = 0.f;
        #pragma unroll
        for (int j = 0; j < 8; j++) {
            int c = lane + (j << 5);
            float v = sm[c][li];
            if (ADD_MO) { v = fmaf(sk, v, mo[(size_t)li*CDIM + c]); sm[c][li] = v; }
            s += v; s2 += v*v;
        }
        #pragma unroll
        for (int off = 16; off; off >>= 1) {
            s  += __shfl_xor_sync(0xffffffffu, s,  off);
            s2 += __shfl_xor_sync(0xffffffffu, s2, off);
        }
        if (lane == 0) {
            float m = s * (1.f/256.f);
            smean[li] = m;
            srstd[li] = rsqrtf(s2*(1.f/256.f) - m*m + 1e-5f);
        }
    }
    __syncthreads();
    size_t base = ((size_t)b*LSEQ + l0)*CDIM;
    #pragma unroll
    for (int i = 0; i < 32; i++) {
        int idx = tid + i*256, li = idx >> 8, c = idx & 255;
        float v = (sm[c][li] - smean[li])*srstd[li]*g[c] + be[c];
        __nv_bfloat16 hb = __float2bfloat16(v);
        oh[base + (size_t)li*CDIM + c] = hb;
        ol[base + (size_t)li*CDIM + c] = __float2bfloat16(v - __bfloat162float(hb));
    }
}

// ---- causal depthwise conv + SiLU; writes fp32 (scan) + bf16 hi/lo (GEMM) ----
__global__ void conv_kernel(const float* __restrict__ cwf, const float* __restrict__ cbf,
                            const float* __restrict__ cwr, const float* __restrict__ cbr)
{
    int idx = blockIdx.x*256 + threadIdx.x;
    int d = idx & (DI-1), l = (idx >> 9) & (LSEQ-1), b = (idx >> 21) & 7, dir = idx >> 24;
    const float* w = (dir ? cwr : cwf) + d*4;
    float acc = (dir ? cbr : cbf)[d];
    const float* xzb = g_xz + (size_t)b*LSEQ*E2 + d;
    #pragma unroll
    for (int j = 0; j < 4; j++) {
        int ir = l - 3 + j;
        if (ir >= 0) {
            int ls = dir ? (LSEQ-1-ir) : ir;
            acc = fmaf(w[j], xzb[(size_t)ls*E2], acc);
        }
    }
    float s = __fdividef(acc, 1.f + __expf(-acc));
    size_t o = ((size_t)b*LSEQ + l)*DI + d;
    __nv_bfloat16 hb = __float2bfloat16(s);
    __nv_bfloat16 lb = __float2bfloat16(s - __bfloat162float(hb));
    if (dir) { g_xcr[o] = s; g_xcrh[o] = hb; g_xcrl[o] = lb; }
    else     { g_xcf[o] = s; g_xcfh[o] = hb; g_xcfl[o] = lb; }
}

// ================= chunk-parallel selective scan =================
__global__ void __launch_bounds__(256)
scan_p1(const float* __restrict__ dtw_f, const float* __restrict__ dtb_f,
        const float* __restrict__ alog_f,
        const float* __restrict__ dtw_r, const float* __restrict__ dtb_r,
        const float* __restrict__ alog_r)
{
    int tid = threadIdx.x;
    int chunk = blockIdx.x >> 1;
    int d = ((blockIdx.x & 1) << 8) | tid;
    int b = blockIdx.y, dir = blockIdx.z;

    const float* dbl = dir ? g_dblr : g_dblf;
    const float* xc  = dir ? g_xcr  : g_xcf;
    const float* dtw = (dir ? dtw_r : dtw_f) + d*16;
    const float* alg = (dir ? alog_r : alog_f) + d*16;
    float dtb = (dir ? dtb_r : dtb_f)[d];

    float W[16], A[16], h[16];
    bool fast = true;
    #pragma unroll
    for (int n = 0; n < 16; n++) {
        W[n] = dtw[n];
        A[n] = -__expf(alg[n]);
        h[n] = 0.f;
        fast = fast && (fabsf(-A[n] - (float)(n+1)) < 1e-4f*(float)(n+1));
    }

    size_t t0 = (size_t)b*LSEQ + (size_t)chunk*CH;
    const float4* dq = (const float4*)dbl + t0*12;
    const float*  xcp = xc + t0*DI + d;
    float S = 0.f;

    if (fast) {
        for (int l = 0; l < CH; l++) {
            float q[32];
            #pragma unroll
            for (int i = 0; i < 8; i++) ((float4*)q)[i] = dq[(size_t)l*12 + i];
            float xv = xcp[(size_t)l*DI];
            float a0 = dtb, a1 = 0.f, a2 = 0.f, a3 = 0.f;
            #pragma unroll
            for (int k = 0; k < 16; k += 4) {
                a0 = fmaf(q[k+0], W[k+0], a0); a1 = fmaf(q[k+1], W[k+1], a1);
                a2 = fmaf(q[k+2], W[k+2], a2); a3 = fmaf(q[k+3], W[k+3], a3);
            }
            float dt = (a0+a1)+(a2+a3);
            float ed = __expf(dt);
            float sp = (dt > 15.f) ? dt : __logf(1.f + ed);
            S += sp;
            float dtx = sp * xv;
            float pw[16];
            pw[0] = __fdividef(1.f, 1.f + ed);
            #pragma unroll
            for (int n = 1; n < 16; n++) pw[n] = pw[n>>1] * pw[(n-1)>>1];
            #pragma unroll
            for (int n = 0; n < 16; n++) h[n] = fmaf(pw[n], h[n], dtx*q[16+n]);
        }
    } else {
        for (int l = 0; l < CH; l++) {
            float q[32];
            #pragma unroll
            for (int i = 0; i < 8; i++) ((float4*)q)[i] = dq[(size_t)l*12 + i];
            float xv = xcp[(size_t)l*DI];
            float a0 = dtb, a1 = 0.f, a2 = 0.f, a3 = 0.f;
            #pragma unroll
            for (int k = 0; k < 16; k += 4) {
                a0 = fmaf(q[k+0], W[k+0], a0); a1 = fmaf(q[k+1], W[k+1], a1);
                a2 = fmaf(q[k+2], W[k+2], a2); a3 = fmaf(q[k+3], W[k+3], a3);
            }
            float dt = (a0+a1)+(a2+a3);
            float ed = __expf(dt);
            float sp = (dt > 15.f) ? dt : __logf(1.f + ed);
            S += sp;
            float dtx = sp * xv;
            #pragma unroll
            for (int n = 0; n < 16; n++)
                h[n] = fmaf(__expf(sp*A[n]), h[n], dtx*q[16+n]);
        }
    }
    size_t base = (size_t)((dir*8 + b)*NCH + chunk);
    #pragma unroll
    for (int n = 0; n < 16; n++) g_hout[(base*16 + n)*DI + d] = h[n];
    g_S[base*DI + d] = S;
}

__global__ void __launch_bounds__(256)
scan_p2(const float* __restrict__ alog_f, const float* __restrict__ alog_r)
{
    int t = blockIdx.x*256 + threadIdx.x;
    int dir = t >> 12, b = (t >> 9) & 7, d = t & 511;
    const float* alg = (dir ? alog_r : alog_f) + d*16;
    float A[16], H[16];
    bool fast = true;
    #pragma unroll
    for (int n = 0; n < 16; n++) {
        A[n] = -__expf(alg[n]);
        H[n] = 0.f;
        fast = fast && (fabsf(-A[n] - (float)(n+1)) < 1e-4f*(float)(n+1));
    }
    size_t dirb = (size_t)(dir*8 + b);
    for (int c = 0; c < NCH; c++) {
        size_t base = dirb*NCH + c;
        #pragma unroll
        for (int n = 0; n < 16; n++) g_hin[(base*16 + n)*DI + d] = H[n];
        float S = g_S[base*DI + d];
        if (fast) {
            float pw[16];
            pw[0] = __expf(-S);
            #pragma unroll
            for (int n = 1; n < 16; n++) pw[n] = pw[n>>1] * pw[(n-1)>>1];
            #pragma unroll
            for (int n = 0; n < 16; n++)
                H[n] = fmaf(pw[n], H[n], g_hout[(base*16 + n)*DI + d]);
        } else {
            #pragma unroll
            for (int n = 0; n < 16; n++)
                H[n] = fmaf(__expf(A[n]*S), H[n], g_hout[(base*16 + n)*DI + d]);
        }
    }
}

__global__ void __launch_bounds__(256)
scan_p3(const float* __restrict__ dtw_f, const float* __restrict__ dtb_f,
        const float* __restrict__ alog_f, const float* __restrict__ dp_f,
        const float* __restrict__ dtw_r, const float* __restrict__ dtb_r,
        const float* __restrict__ alog_r, const float* __restrict__ dp_r)
{
    int tid = threadIdx.x;
    int chunk = blockIdx.x >> 1;
    int d = ((blockIdx.x & 1) << 8) | tid;
    int b = blockIdx.y, dir = blockIdx.z;

    const float* dbl = dir ? g_dblr : g_dblf;
    const float* xc  = dir ? g_xcr  : g_xcf;
    const float* dtw = (dir ? dtw_r : dtw_f) + d*16;
    const float* alg = (dir ? alog_r : alog_f) + d*16;
    float dtb = (dir ? dtb_r : dtb_f)[d];
    float Dpv = (dir ? dp_r  : dp_f )[d];

    float W[16], A[16], h[16];
    bool fast = true;
    size_t base = (size_t)((dir*8 + b)*NCH + chunk);
    #pragma unroll
    for (int n = 0; n < 16; n++) {
        W[n] = dtw[n];
        A[n] = -__expf(alg[n]);
        h[n] = g_hin[(base*16 + n)*DI + d];
        fast = fast && (fabsf(-A[n] - (float)(n+1)) < 1e-4f*(float)(n+1));
    }

    size_t t0 = (size_t)b*LSEQ + (size_t)chunk*CH;
    const float4* dq = (const float4*)dbl + t0*12;
    const float*  xcp = xc + t0*DI + d;
    const float*  zb  = g_xz + (size_t)b*LSEQ*E2 + DI + d;
    float* yp = (dir ? g_yr : g_yf) + (size_t)b*LSEQ*DI + d;

    for (int l = 0; l < CH; l++) {
        float q[48];
        #pragma unroll
        for (int i = 0; i < 12; i++) ((float4*)q)[i] = dq[(size_t)l*12 + i];
        float xv = xcp[(size_t)l*DI];
        int lf = chunk*CH + l;
        int zl = dir ? (LSEQ-1-lf) : lf;
        float zv = zb[(size_t)zl*E2];

        float a0 = dtb, a1 = 0.f, a2 = 0.f, a3 = 0.f;
        #pragma unroll
        for (int k = 0; k < 16; k += 4) {
            a0 = fmaf(q[k+0], W[k+0], a0); a1 = fmaf(q[k+1], W[k+1], a1);
            a2 = fmaf(q[k+2], W[k+2], a2); a3 = fmaf(q[k+3], W[k+3], a3);
        }
        float dt = (a0+a1)+(a2+a3);
        float ed = __expf(dt);
        float sp = (dt > 15.f) ? dt : __logf(1.f + ed);
        float dtx = sp * xv;
        float y0 = 0.f, y1 = 0.f, y2 = 0.f, y3 = 0.f;
        if (fast) {
            float pw[16];
            pw[0] = __fdividef(1.f, 1.f + ed);
            #pragma unroll
            for (int n = 1; n < 16; n++) pw[n] = pw[n>>1] * pw[(n-1)>>1];
            #pragma unroll
            for (int n = 0; n < 16; n += 4) {
                h[n+0] = fmaf(pw[n+0], h[n+0], dtx*q[16+n+0]); y0 = fmaf(h[n+0], q[32+n+0], y0);
                h[n+1] = fmaf(pw[n+1], h[n+1], dtx*q[16+n+1]); y1 = fmaf(h[n+1], q[32+n+1], y1);
                h[n+2] = fmaf(pw[n+2], h[n+2], dtx*q[16+n+2]); y2 = fmaf(h[n+2], q[32+n+2], y2);
                h[n+3] = fmaf(pw[n+3], h[n+3], dtx*q[16+n+3]); y3 = fmaf(h[n+3], q[32+n+3], y3);
            }
        } else {
            #pragma unroll
            for (int n = 0; n < 16; n++) {
                h[n] = fmaf(__expf(sp*A[n]), h[n], dtx*q[16+n]);
                y0 = fmaf(h[n], q[32+n], y0);
            }
        }
        float y = (y0+y1)+(y2+y3);
        float sz = __fdividef(zv, 1.f + __expf(-zv));
        int sl = dir ? (LSEQ-1-lf) : lf;
        yp[(size_t)sl*DI] = fmaf(Dpv, xv, y) * sz;
    }
}

// ================= launch =================
extern "C" void kernel_launch(void* const* d_in, const int* in_sizes, int n_in,
                              void* d_out, int out_size)
{
    const float* x       = (const float*)d_in[0];
    const float* norm_g  = (const float*)d_in[1];
    const float* norm_b  = (const float*)d_in[2];
    const float* skip    = (const float*)d_in[3];
    const float* proj_w  = (const float*)d_in[4];
    const float* proj_b  = (const float*)d_in[5];
    const float* in_w    = (const float*)d_in[6];
    const float* out_w   = (const float*)d_in[7];
    const float* cwf     = (const float*)d_in[8];
    const float* cbf     = (const float*)d_in[9];
    const float* xpw_f   = (const float*)d_in[10];
    const float* dtw_f   = (const float*)d_in[11];
    const float* dtb_f   = (const float*)d_in[12];
    const float* alog_f  = (const float*)d_in[13];
    const float* dp_f    = (const float*)d_in[14];
    const float* cwr     = (const float*)d_in[15];
    const float* cbr     = (const float*)d_in[16];
    const float* xpw_r   = (const float*)d_in[17];
    const float* dtw_r   = (const float*)d_in[18];
    const float* dtb_r   = (const float*)d_in[19];
    const float* alog_r  = (const float*)d_in[20];
    const float* dp_r    = (const float*)d_in[21];
    float* out = (float*)d_out;

    #define SYM(p, s) float* p; cudaGetSymbolAddress((void**)&p, s)
    #define SYMB(p, s) __nv_bfloat16* p; cudaGetSymbolAddress((void**)&p, s)
    SYM(p_xz, g_xz); SYM(p_dblf, g_dblf); SYM(p_dblr, g_dblr);
    SYM(p_yf, g_yf); SYM(p_yr, g_yr); SYM(p_mo, g_mo);
    SYMB(p_xnh, g_xnh);  SYMB(p_xnl, g_xnl);
    SYMB(p_xcfh, g_xcfh); SYMB(p_xcfl, g_xcfl);
    SYMB(p_xcrh, g_xcrh); SYMB(p_xcrl, g_xcrl);
    SYMB(p_ysh, g_ysh);  SYMB(p_ysl, g_ysl);
    SYMB(p_xmnh, g_xmnh); SYMB(p_xmnl, g_xmnl);
    SYMB(p_inwh, g_inwh); SYMB(p_inwl, g_inwl);
    SYMB(p_owh, g_owh);  SYMB(p_owl, g_owl);
    SYMB(p_pwh, g_pwh);  SYMB(p_pwl, g_pwl);
    SYMB(p_xpfh, g_xpfh); SYMB(p_xpfl, g_xpfl);
    SYMB(p_xprh, g_xprh); SYMB(p_xprl, g_xprl);

    // weight splits
    split_kernel<<<(E2*CDIM+255)/256, 256>>>(in_w, p_inwh, p_inwl, E2*CDIM);
    split_kernel<<<(CDIM*DI+255)/256, 256>>>(out_w, p_owh, p_owl, CDIM*DI);
    split_kernel<<<(CDIM*CDIM+255)/256, 256>>>(proj_w, p_pwh, p_pwl, CDIM*CDIM);
    split_kernel<<<(48*DI+255)/256, 256>>>(xpw_f, p_xpfh, p_xpfl, 48*DI);
    split_kernel<<<(48*DI+255)/256, 256>>>(xpw_r, p_xprh, p_xprl, 48*DI);

    dim3 lng(LSEQ/32, BB);
    ln_kernel<false><<<lng, 256>>>(x, norm_g, norm_b, skip, p_xnh, p_xnl);

    gemm_mma<false,false><<<dim3(NTOK/128, E2/64), 256>>>(
        CDIM, p_xnh, p_xnl, p_inwh, p_inwl, p_xz, E2, E2, nullptr);

    conv_kernel<<<(2*NTOK*DI)/256, 256>>>(cwf, cbf, cwr, cbr);

    gemm_mma<false,false><<<dim3(NTOK/128, 1), 256>>>(
        DI, p_xcfh, p_xcfl, p_xpfh, p_xpfl, p_dblf, 48, 48, nullptr);
    gemm_mma<false,false><<<dim3(NTOK/128, 1), 256>>>(
        DI, p_xcrh, p_xcrl, p_xprh, p_xprl, p_dblr, 48, 48, nullptr);

    dim3 sg(2*NCH, BB, 2);
    scan_p1<<<sg, 256>>>(dtw_f, dtb_f, alog_f, dtw_r, dtb_r, alog_r);
    scan_p2<<<32, 256>>>(alog_f, alog_r);
    scan_p3<<<sg, 256>>>(dtw_f, dtb_f, alog_f, dp_f, dtw_r, dtb_r, alog_r, dp_r);

    ysum_split<<<(NTOK*DI)/256, 256>>>(p_yf, p_yr, p_ysh, p_ysl);

    gemm_mma<false,false><<<dim3(NTOK/128, CDIM/64), 256>>>(
        DI, p_ysh, p_ysl, p_owh, p_owl, p_mo, CDIM, CDIM, nullptr);

    ln_kernel<true><<<lng, 256>>>(x, norm_g, norm_b, skip, p_xmnh, p_xmnl);

    gemm_mma<true,true><<<dim3(NTOK/128, CDIM/64), 256>>>(
        CDIM, p_xmnh, p_xmnl, p_pwh, p_pwl, out, CDIM, CDIM, proj_b);
}